// round 1
// baseline (speedup 1.0000x reference)
#include <cuda_runtime.h>
#include <math.h>

#define Bsz   128
#define Wd    128
#define FIN   64
#define NN    64
#define EE    4096
#define EDd   16
#define HC    128
#define FLATd 8192
#define HIDd  2048
#define SPLITK 8

// ---------------- scratch (static device globals; no allocation) ----------------
__device__ __align__(128) float g_xg[Bsz * NN * Wd];          // 4 MB  [b][n][w]
__device__ __align__(128) float g_h[Bsz * NN * HC];           // 4 MB  [b][n][t]
__device__ __align__(128) float g_xflat[Bsz * FLATd];         // 4 MB  [b][n*128+t]
__device__ __align__(128) float g_h1part[SPLITK * Bsz * HIDd];// 8 MB
__device__ __align__(128) float g_h1[Bsz * HIDd];             // 1 MB
__device__ int g_csr_off[NN + 1];
__device__ int g_csr_edges[EE];

// ---------------- CSR build: group edges by destination node ----------------
__global__ void k_csr(const int* __restrict__ ei) {
    __shared__ int cnt[NN];
    __shared__ int off[NN + 1];
    __shared__ int cur[NN];
    int tid = threadIdx.x;
    if (tid < NN) cnt[tid] = 0;
    __syncthreads();
    for (int e = tid; e < EE; e += blockDim.x)
        atomicAdd(&cnt[ei[EE + e]], 1);     // row 1 = dst
    __syncthreads();
    if (tid == 0) {
        int run = 0;
        for (int k = 0; k < NN; k++) { off[k] = run; cur[k] = run; run += cnt[k]; }
        off[NN] = run;
    }
    __syncthreads();
    for (int e = tid; e < EE; e += blockDim.x) {
        int d = ei[EE + e];
        int pos = atomicAdd(&cur[d], 1);
        g_csr_edges[pos] = e;
    }
    if (tid <= NN) g_csr_off[tid] = off[tid];
}

// ---------------- TCN: conv1d(k=3, pad=1)  x[B,W,FIN] -> g_xg[B,N,W] ----------------
__global__ void k_tcn(const float* __restrict__ x,
                      const float* __restrict__ tw,
                      const float* __restrict__ tb) {
    __shared__ float xs[FIN * 129];   // [i][w], pitch 129 -> conflict-free
    __shared__ float sw[16 * 192];    // 16 output channels' weights
    int b = blockIdx.y, nc = blockIdx.x;   // nc: chunk of 16 n's
    int tid = threadIdx.x;                 // 128 threads = w
    const float* xb = x + (size_t)b * Wd * FIN;
    for (int idx = tid; idx < Wd * FIN; idx += 128) {
        int w = idx >> 6, i = idx & 63;
        xs[i * 129 + w] = xb[idx];
    }
    for (int idx = tid; idx < 16 * 192; idx += 128)
        sw[idx] = tw[nc * 16 * 192 + idx];
    __syncthreads();

    int w = tid;
    float acc[16];
#pragma unroll
    for (int nl = 0; nl < 16; nl++) acc[nl] = tb[nc * 16 + nl];
    for (int i = 0; i < FIN; i++) {
        float x0 = xs[i * 129 + w];
        float xm = (w > 0)   ? xs[i * 129 + w - 1] : 0.f;
        float xp = (w < 127) ? xs[i * 129 + w + 1] : 0.f;
#pragma unroll
        for (int nl = 0; nl < 16; nl++) {
            const float* wp = &sw[nl * 192 + i * 3];
            acc[nl] += xm * wp[0] + x0 * wp[1] + xp * wp[2];
        }
    }
#pragma unroll
    for (int nl = 0; nl < 16; nl++)
        g_xg[((size_t)b * NN + nc * 16 + nl) * Wd + w] = acc[nl];
}

// ---------------- lin_l: g_h[b,n,o] = xg[b,n,:] @ lin_l_w[o,:]^T + b ----------------
__global__ void k_linl(const float* __restrict__ lw, const float* __restrict__ lb) {
    __shared__ float xs[NN * 129];   // [n][w]
    __shared__ float ws[64 * 33];    // [o_local][w_local], 32-w chunks
    int b = blockIdx.y, oc = blockIdx.x;   // o base = oc*64
    int tid = threadIdx.x;                 // 256
    for (int idx = tid; idx < NN * Wd; idx += 256) {
        int n = idx >> 7, w = idx & 127;
        xs[n * 129 + w] = g_xg[(size_t)b * NN * Wd + idx];
    }
    int tx = tid & 15, ty = tid >> 4;      // 16x16 thread grid, 4x4 per thread
    float acc[4][4];
#pragma unroll
    for (int i = 0; i < 4; i++)
#pragma unroll
        for (int j = 0; j < 4; j++) acc[i][j] = 0.f;

    for (int wc = 0; wc < 4; wc++) {
        __syncthreads();
        for (int idx = tid; idx < 64 * 32; idx += 256) {
            int ol = idx >> 5, wl = idx & 31;
            ws[ol * 33 + wl] = lw[(oc * 64 + ol) * Wd + wc * 32 + wl];
        }
        __syncthreads();
#pragma unroll 4
        for (int wl = 0; wl < 32; wl++) {
            float a[4], bb[4];
#pragma unroll
            for (int j = 0; j < 4; j++) a[j]  = xs[(ty * 4 + j) * 129 + wc * 32 + wl];
#pragma unroll
            for (int j = 0; j < 4; j++) bb[j] = ws[(tx * 4 + j) * 33 + wl];
#pragma unroll
            for (int i = 0; i < 4; i++)
#pragma unroll
                for (int j = 0; j < 4; j++) acc[i][j] += a[i] * bb[j];
        }
    }
#pragma unroll
    for (int i = 0; i < 4; i++)
#pragma unroll
        for (int j = 0; j < 4; j++) {
            int n = ty * 4 + i, o = oc * 64 + tx * 4 + j;
            g_h[((size_t)b * NN + n) * HC + o] = acc[i][j] + lb[o];
        }
}

// ---------------- GAT: per (node, batch) block; 4 warps = 4 heads; online softmax ----------------
__global__ void k_gat(const int* __restrict__ ei,
                      const float* __restrict__ eattr,
                      const float* __restrict__ lew,
                      const float* __restrict__ leb,
                      const float* __restrict__ att) {
    int n = blockIdx.x, b = blockIdx.y;
    int t = threadIdx.x;                   // 128 = h*32 + c
    const float4* w4 = (const float4*)(lew + t * EDd);
    float4 w0 = w4[0], w1 = w4[1], w2 = w4[2], w3 = w4[3];
    float eb = leb[t];
    float att_t = att[t];
    float hd = g_h[((size_t)b * NN + n) * HC + t];

    int beg = g_csr_off[n], end = g_csr_off[n + 1];
    float m = -1e30f, ssum = 0.f, acc = 0.f;

    for (int j = beg; j < end; j++) {
        int e = g_csr_edges[j];
        int s = ei[e];                     // row 0 = src
        const float4* ea4 = (const float4*)(eattr + ((size_t)b * EE + e) * EDd);
        float4 q0 = ea4[0], q1 = ea4[1], q2 = ea4[2], q3 = ea4[3];
        float ev = eb
            + q0.x * w0.x + q0.y * w0.y + q0.z * w0.z + q0.w * w0.w
            + q1.x * w1.x + q1.y * w1.y + q1.z * w1.z + q1.w * w1.w
            + q2.x * w2.x + q2.y * w2.y + q2.z * w2.z + q2.w * w2.w
            + q3.x * w3.x + q3.y * w3.y + q3.z * w3.z + q3.w * w3.w;
        float hs = g_h[((size_t)b * NN + s) * HC + t];
        float z = hd + hs + ev;
        float a = fmaxf(z, 0.01f * z);     // leaky_relu
        float p = a * att_t;
        p += __shfl_xor_sync(0xffffffffu, p, 16);
        p += __shfl_xor_sync(0xffffffffu, p, 8);
        p += __shfl_xor_sync(0xffffffffu, p, 4);
        p += __shfl_xor_sync(0xffffffffu, p, 2);
        p += __shfl_xor_sync(0xffffffffu, p, 1);
        float nm = fmaxf(m, p);
        float we = __expf(p - nm);
        float sc = __expf(m - nm);
        ssum = ssum * sc + we;
        acc  = acc  * sc + hs * we;
        m = nm;
    }
    float v = acc / (ssum + 1e-16f);
    float o = (v > 0.f) ? v : expm1f(v);   // elu
    g_xflat[(size_t)b * FLATd + n * HC + t] = o;
}

// ---------------- fc1 GEMM: 128x2048x8192, tile 128x128x16, split-K=8 ----------------
__global__ void k_fc1(const float* __restrict__ wq) {
    __shared__ float sA[16 * 132];
    __shared__ float sB[16 * 132];
    int ntile = blockIdx.x << 7;
    int k0base = blockIdx.y << 10;
    int tid = threadIdx.x;
    int lm = tid & 127, lk = (tid >> 7) << 3;
    int tx = tid & 15, ty = tid >> 4;

    float acc[8][8];
#pragma unroll
    for (int i = 0; i < 8; i++)
#pragma unroll
        for (int j = 0; j < 8; j++) acc[i][j] = 0.f;

    const float* Aptr = g_xflat + (size_t)lm * FLATd + k0base + lk;
    const float* Bptr = wq + (size_t)(ntile + lm) * FLATd + k0base + lk;

    for (int kt = 0; kt < 64; kt++) {
        float4 a0 = *(const float4*)(Aptr);
        float4 a1 = *(const float4*)(Aptr + 4);
        float4 b0 = *(const float4*)(Bptr);
        float4 b1 = *(const float4*)(Bptr + 4);
        sA[(lk + 0) * 132 + lm] = a0.x; sA[(lk + 1) * 132 + lm] = a0.y;
        sA[(lk + 2) * 132 + lm] = a0.z; sA[(lk + 3) * 132 + lm] = a0.w;
        sA[(lk + 4) * 132 + lm] = a1.x; sA[(lk + 5) * 132 + lm] = a1.y;
        sA[(lk + 6) * 132 + lm] = a1.z; sA[(lk + 7) * 132 + lm] = a1.w;
        sB[(lk + 0) * 132 + lm] = b0.x; sB[(lk + 1) * 132 + lm] = b0.y;
        sB[(lk + 2) * 132 + lm] = b0.z; sB[(lk + 3) * 132 + lm] = b0.w;
        sB[(lk + 4) * 132 + lm] = b1.x; sB[(lk + 5) * 132 + lm] = b1.y;
        sB[(lk + 6) * 132 + lm] = b1.z; sB[(lk + 7) * 132 + lm] = b1.w;
        __syncthreads();
#pragma unroll
        for (int kk = 0; kk < 16; kk++) {
            float af[8], bf[8];
            *(float4*)af       = *(const float4*)&sA[kk * 132 + ty * 8];
            *(float4*)(af + 4) = *(const float4*)&sA[kk * 132 + ty * 8 + 4];
            *(float4*)bf       = *(const float4*)&sB[kk * 132 + tx * 8];
            *(float4*)(bf + 4) = *(const float4*)&sB[kk * 132 + tx * 8 + 4];
#pragma unroll
            for (int i = 0; i < 8; i++)
#pragma unroll
                for (int j = 0; j < 8; j++) acc[i][j] += af[i] * bf[j];
        }
        __syncthreads();
        Aptr += 16; Bptr += 16;
    }
    float* outp = g_h1part + (size_t)blockIdx.y * (Bsz * HIDd);
#pragma unroll
    for (int i = 0; i < 8; i++)
#pragma unroll
        for (int j = 0; j < 8; j++)
            outp[(size_t)(ty * 8 + i) * HIDd + ntile + tx * 8 + j] = acc[i][j];
}

// ---------------- split-K reduce + bias + BN(eval) + ReLU ----------------
__global__ void k_bnrelu(const float* __restrict__ fb,
                         const float* __restrict__ g,
                         const float* __restrict__ beta) {
    int gid = blockIdx.x * 256 + threadIdx.x;
    float s = 0.f;
#pragma unroll
    for (int p = 0; p < SPLITK; p++) s += g_h1part[(size_t)p * (Bsz * HIDd) + gid];
    int o = gid & (HIDd - 1);
    float val = (s + fb[o]) * (g[o] * rsqrtf(1.f + 1e-5f)) + beta[o];
    g_h1[gid] = fmaxf(val, 0.f);
}

// ---------------- fc2: [128,2048] @ [2,2048]^T ----------------
__global__ void k_fc2(const float* __restrict__ w2, const float* __restrict__ b2,
                      float* __restrict__ out) {
    int b = blockIdx.x, tid = threadIdx.x;
    float a0 = 0.f, a1 = 0.f;
    for (int o = tid; o < HIDd; o += 256) {
        float h = g_h1[(size_t)b * HIDd + o];
        a0 += h * w2[o];
        a1 += h * w2[HIDd + o];
    }
    __shared__ float r0[256], r1[256];
    r0[tid] = a0; r1[tid] = a1;
    __syncthreads();
    for (int s = 128; s > 0; s >>= 1) {
        if (tid < s) { r0[tid] += r0[tid + s]; r1[tid] += r1[tid + s]; }
        __syncthreads();
    }
    if (tid == 0) {
        out[b * 2 + 0] = r0[0] + b2[0];
        out[b * 2 + 1] = r1[0] + b2[1];
    }
}

extern "C" void kernel_launch(void* const* d_in, const int* in_sizes, int n_in,
                              void* d_out, int out_size) {
    const float* x       = (const float*)d_in[0];
    const int*   ei      = (const int*)  d_in[1];
    const float* eattr   = (const float*)d_in[2];
    const float* tcn_w   = (const float*)d_in[3];
    const float* tcn_b   = (const float*)d_in[4];
    const float* lin_l_w = (const float*)d_in[5];
    const float* lin_l_b = (const float*)d_in[6];
    const float* lin_e_w = (const float*)d_in[7];
    const float* lin_e_b = (const float*)d_in[8];
    const float* att     = (const float*)d_in[9];
    const float* fc1_w   = (const float*)d_in[10];
    const float* fc1_b   = (const float*)d_in[11];
    const float* bn_g    = (const float*)d_in[12];
    const float* bn_b    = (const float*)d_in[13];
    const float* fc2_w   = (const float*)d_in[14];
    const float* fc2_b   = (const float*)d_in[15];
    float* out = (float*)d_out;

    k_csr<<<1, 256>>>(ei);
    k_tcn<<<dim3(4, Bsz), 128>>>(x, tcn_w, tcn_b);
    k_linl<<<dim3(2, Bsz), 256>>>(lin_l_w, lin_l_b);
    k_gat<<<dim3(NN, Bsz), 128>>>(ei, eattr, lin_e_w, lin_e_b, att);
    k_fc1<<<dim3(16, SPLITK), 256>>>(fc1_w);
    k_bnrelu<<<(Bsz * HIDd) / 256, 256>>>(fc1_b, bn_g, bn_b);
    k_fc2<<<Bsz, 256>>>(fc2_w, fc2_b, out);
}

// round 2
// speedup vs baseline: 1.0424x; 1.0424x over previous
#include <cuda_runtime.h>
#include <math.h>

#define Bsz   128
#define Wd    128
#define FIN   64
#define NN    64
#define EE    4096
#define EDd   16
#define HC    128
#define FLATd 8192
#define HIDd  2048
#define SPLITK 8

// ---------------- scratch (static device globals; no allocation) ----------------
__device__ __align__(128) float g_xg[Bsz * NN * Wd];
__device__ __align__(128) float g_h[Bsz * NN * HC];
__device__ __align__(128) float g_xflat[Bsz * FLATd];
__device__ __align__(128) float g_h1part[SPLITK * Bsz * HIDd];
__device__ __align__(128) float g_h1[Bsz * HIDd];
__device__ int  g_csr_off[NN + 1];
__device__ int2 g_csr_es[EE];            // (edge_id, src_node) packed -> one LDG.64

// ---------------- f32x2 packed-FMA helpers (FFMA2; PTX-only on sm_103a) --------
__device__ __forceinline__ unsigned long long pk2(float lo, float hi) {
    unsigned long long r;
    asm("mov.b64 %0, {%1,%2};" : "=l"(r) : "f"(lo), "f"(hi));
    return r;
}
__device__ __forceinline__ void fma2(unsigned long long& d,
                                     unsigned long long a, unsigned long long b) {
    asm("fma.rn.f32x2 %0, %1, %2, %0;" : "+l"(d) : "l"(a), "l"(b));
}
__device__ __forceinline__ float2 upk2(unsigned long long v) {
    float2 r;
    asm("mov.b64 {%0,%1}, %2;" : "=f"(r.x), "=f"(r.y) : "l"(v));
    return r;
}

// ---------------- CSR build: group edges by destination node ----------------
__global__ void k_csr(const int* __restrict__ ei) {
    __shared__ int cnt[NN];
    __shared__ int off[NN + 1];
    __shared__ int cur[NN];
    int tid = threadIdx.x;
    if (tid < NN) cnt[tid] = 0;
    __syncthreads();
    for (int e = tid; e < EE; e += blockDim.x)
        atomicAdd(&cnt[ei[EE + e]], 1);     // row 1 = dst
    __syncthreads();
    if (tid == 0) {
        int run = 0;
        for (int k = 0; k < NN; k++) { off[k] = run; cur[k] = run; run += cnt[k]; }
        off[NN] = run;
    }
    __syncthreads();
    for (int e = tid; e < EE; e += blockDim.x) {
        int d = ei[EE + e];
        int pos = atomicAdd(&cur[d], 1);
        g_csr_es[pos] = make_int2(e, ei[e]);   // src in row 0
    }
    if (tid <= NN) g_csr_off[tid] = off[tid];
}

// ---------------- TCN: conv1d(k=3, pad=1)  x[B,W,FIN] -> g_xg[B,N,W] ----------------
__global__ void k_tcn(const float* __restrict__ x,
                      const float* __restrict__ tw,
                      const float* __restrict__ tb) {
    __shared__ float xs[FIN * 129];
    __shared__ float sw[16 * 192];
    int b = blockIdx.y, nc = blockIdx.x;
    int tid = threadIdx.x;
    const float* xb = x + (size_t)b * Wd * FIN;
    for (int idx = tid; idx < Wd * FIN; idx += 128) {
        int w = idx >> 6, i = idx & 63;
        xs[i * 129 + w] = xb[idx];
    }
    for (int idx = tid; idx < 16 * 192; idx += 128)
        sw[idx] = tw[nc * 16 * 192 + idx];
    __syncthreads();

    int w = tid;
    float acc[16];
#pragma unroll
    for (int nl = 0; nl < 16; nl++) acc[nl] = tb[nc * 16 + nl];
    for (int i = 0; i < FIN; i++) {
        float x0 = xs[i * 129 + w];
        float xm = (w > 0)   ? xs[i * 129 + w - 1] : 0.f;
        float xp = (w < 127) ? xs[i * 129 + w + 1] : 0.f;
#pragma unroll
        for (int nl = 0; nl < 16; nl++) {
            const float* wp = &sw[nl * 192 + i * 3];
            acc[nl] += xm * wp[0] + x0 * wp[1] + xp * wp[2];
        }
    }
#pragma unroll
    for (int nl = 0; nl < 16; nl++)
        g_xg[((size_t)b * NN + nc * 16 + nl) * Wd + w] = acc[nl];
}

// ---------------- lin_l: g_h[b,n,o] = xg[b,n,:] @ lin_l_w[o,:]^T + b ----------------
__global__ void k_linl(const float* __restrict__ lw, const float* __restrict__ lb) {
    __shared__ float xs[NN * 129];
    __shared__ float ws[64 * 33];
    int b = blockIdx.y, oc = blockIdx.x;
    int tid = threadIdx.x;
    for (int idx = tid; idx < NN * Wd; idx += 256) {
        int n = idx >> 7, w = idx & 127;
        xs[n * 129 + w] = g_xg[(size_t)b * NN * Wd + idx];
    }
    int tx = tid & 15, ty = tid >> 4;
    float acc[4][4];
#pragma unroll
    for (int i = 0; i < 4; i++)
#pragma unroll
        for (int j = 0; j < 4; j++) acc[i][j] = 0.f;

    for (int wc = 0; wc < 4; wc++) {
        __syncthreads();
        for (int idx = tid; idx < 64 * 32; idx += 256) {
            int ol = idx >> 5, wl = idx & 31;
            ws[ol * 33 + wl] = lw[(oc * 64 + ol) * Wd + wc * 32 + wl];
        }
        __syncthreads();
#pragma unroll 4
        for (int wl = 0; wl < 32; wl++) {
            float a[4], bb[4];
#pragma unroll
            for (int j = 0; j < 4; j++) a[j]  = xs[(ty * 4 + j) * 129 + wc * 32 + wl];
#pragma unroll
            for (int j = 0; j < 4; j++) bb[j] = ws[(tx * 4 + j) * 33 + wl];
#pragma unroll
            for (int i = 0; i < 4; i++)
#pragma unroll
                for (int j = 0; j < 4; j++) acc[i][j] += a[i] * bb[j];
        }
    }
#pragma unroll
    for (int i = 0; i < 4; i++)
#pragma unroll
        for (int j = 0; j < 4; j++) {
            int n = ty * 4 + i, o = oc * 64 + tx * 4 + j;
            g_h[((size_t)b * NN + n) * HC + o] = acc[i][j] + lb[o];
        }
}

// ---------------- GAT: 2-edge unrolled dual-state online softmax ----------------
__global__ void __launch_bounds__(128) k_gat(const float* __restrict__ eattr,
                      const float* __restrict__ lew,
                      const float* __restrict__ leb,
                      const float* __restrict__ att) {
    int n = blockIdx.x, b = blockIdx.y;
    int t = threadIdx.x;                   // 128 = h*32 + c
    const float4* w4 = (const float4*)(lew + t * EDd);
    float4 w0 = w4[0], w1 = w4[1], w2 = w4[2], w3 = w4[3];
    float eb = leb[t];
    float att_t = att[t];
    const float* hb = g_h + (size_t)b * NN * HC;
    float hd = hb[n * HC + t];

    int beg = g_csr_off[n], end = g_csr_off[n + 1];
    int deg = end - beg;
    const int2* lst = g_csr_es + beg;
    const float4* eab = (const float4*)eattr + (size_t)b * EE * 4;

    float m0 = -1e30f, s0 = 0.f, a0 = 0.f;
    float m1 = -1e30f, s1 = 0.f, a1 = 0.f;

    int j = 0;
    for (; j + 2 <= deg; j += 2) {
        int2 p0 = lst[j];
        int2 p1 = lst[j + 1];
        const float4* A0 = eab + p0.x * 4;
        const float4* A1 = eab + p1.x * 4;
        float4 q00 = A0[0], q01 = A0[1], q02 = A0[2], q03 = A0[3];
        float4 q10 = A1[0], q11 = A1[1], q12 = A1[2], q13 = A1[3];
        float hs0 = hb[p0.y * HC + t];
        float hs1 = hb[p1.y * HC + t];

        float ev0 = eb
            + q00.x * w0.x + q00.y * w0.y + q00.z * w0.z + q00.w * w0.w
            + q01.x * w1.x + q01.y * w1.y + q01.z * w1.z + q01.w * w1.w
            + q02.x * w2.x + q02.y * w2.y + q02.z * w2.z + q02.w * w2.w
            + q03.x * w3.x + q03.y * w3.y + q03.z * w3.z + q03.w * w3.w;
        float ev1 = eb
            + q10.x * w0.x + q10.y * w0.y + q10.z * w0.z + q10.w * w0.w
            + q11.x * w1.x + q11.y * w1.y + q11.z * w1.z + q11.w * w1.w
            + q12.x * w2.x + q12.y * w2.y + q12.z * w2.z + q12.w * w2.w
            + q13.x * w3.x + q13.y * w3.y + q13.z * w3.z + q13.w * w3.w;

        float z0 = hd + hs0 + ev0;
        float z1 = hd + hs1 + ev1;
        float x0 = fmaxf(z0, 0.01f * z0) * att_t;
        float x1 = fmaxf(z1, 0.01f * z1) * att_t;
        // interleaved butterfly reductions (two independent chains)
        x0 += __shfl_xor_sync(0xffffffffu, x0, 16);
        x1 += __shfl_xor_sync(0xffffffffu, x1, 16);
        x0 += __shfl_xor_sync(0xffffffffu, x0, 8);
        x1 += __shfl_xor_sync(0xffffffffu, x1, 8);
        x0 += __shfl_xor_sync(0xffffffffu, x0, 4);
        x1 += __shfl_xor_sync(0xffffffffu, x1, 4);
        x0 += __shfl_xor_sync(0xffffffffu, x0, 2);
        x1 += __shfl_xor_sync(0xffffffffu, x1, 2);
        x0 += __shfl_xor_sync(0xffffffffu, x0, 1);
        x1 += __shfl_xor_sync(0xffffffffu, x1, 1);
        // independent online-softmax state updates
        float nm0 = fmaxf(m0, x0);
        float we0 = __expf(x0 - nm0);
        float sc0 = __expf(m0 - nm0);
        s0 = s0 * sc0 + we0;
        a0 = a0 * sc0 + hs0 * we0;
        m0 = nm0;
        float nm1 = fmaxf(m1, x1);
        float we1 = __expf(x1 - nm1);
        float sc1 = __expf(m1 - nm1);
        s1 = s1 * sc1 + we1;
        a1 = a1 * sc1 + hs1 * we1;
        m1 = nm1;
    }
    if (j < deg) {   // odd tail -> state 0
        int2 p0 = lst[j];
        const float4* A0 = eab + p0.x * 4;
        float4 q00 = A0[0], q01 = A0[1], q02 = A0[2], q03 = A0[3];
        float hs0 = hb[p0.y * HC + t];
        float ev0 = eb
            + q00.x * w0.x + q00.y * w0.y + q00.z * w0.z + q00.w * w0.w
            + q01.x * w1.x + q01.y * w1.y + q01.z * w1.z + q01.w * w1.w
            + q02.x * w2.x + q02.y * w2.y + q02.z * w2.z + q02.w * w2.w
            + q03.x * w3.x + q03.y * w3.y + q03.z * w3.z + q03.w * w3.w;
        float z0 = hd + hs0 + ev0;
        float x0 = fmaxf(z0, 0.01f * z0) * att_t;
        x0 += __shfl_xor_sync(0xffffffffu, x0, 16);
        x0 += __shfl_xor_sync(0xffffffffu, x0, 8);
        x0 += __shfl_xor_sync(0xffffffffu, x0, 4);
        x0 += __shfl_xor_sync(0xffffffffu, x0, 2);
        x0 += __shfl_xor_sync(0xffffffffu, x0, 1);
        float nm0 = fmaxf(m0, x0);
        float we0 = __expf(x0 - nm0);
        float sc0 = __expf(m0 - nm0);
        s0 = s0 * sc0 + we0;
        a0 = a0 * sc0 + hs0 * we0;
        m0 = nm0;
    }
    // merge dual states
    float mm = fmaxf(m0, m1);
    float c0 = __expf(m0 - mm);
    float c1 = __expf(m1 - mm);
    float ss = s0 * c0 + s1 * c1;
    float ac = a0 * c0 + a1 * c1;
    float v = ac / (ss + 1e-16f);
    float o = (v > 0.f) ? v : expm1f(v);   // elu
    g_xflat[(size_t)b * FLATd + n * HC + t] = o;
}

// ---------------- fc1 GEMM: 128x2048x8192, tile 128x128x16, split-K=8, FFMA2 ----------------
__global__ void __launch_bounds__(256) k_fc1(const float* __restrict__ wq) {
    __shared__ float sA[16 * 132];
    __shared__ float sB[16 * 132];
    int ntile = blockIdx.x << 7;
    int k0base = blockIdx.y << 10;
    int tid = threadIdx.x;
    int lm = tid & 127, lk = (tid >> 7) << 3;
    int tx = tid & 15, ty = tid >> 4;

    unsigned long long acc2[8][4];
#pragma unroll
    for (int i = 0; i < 8; i++)
#pragma unroll
        for (int jp = 0; jp < 4; jp++) acc2[i][jp] = 0ull;

    const float* Aptr = g_xflat + (size_t)lm * FLATd + k0base + lk;
    const float* Bptr = wq + (size_t)(ntile + lm) * FLATd + k0base + lk;

    for (int kt = 0; kt < 64; kt++) {
        float4 a0 = *(const float4*)(Aptr);
        float4 a1 = *(const float4*)(Aptr + 4);
        float4 b0 = *(const float4*)(Bptr);
        float4 b1 = *(const float4*)(Bptr + 4);
        sA[(lk + 0) * 132 + lm] = a0.x; sA[(lk + 1) * 132 + lm] = a0.y;
        sA[(lk + 2) * 132 + lm] = a0.z; sA[(lk + 3) * 132 + lm] = a0.w;
        sA[(lk + 4) * 132 + lm] = a1.x; sA[(lk + 5) * 132 + lm] = a1.y;
        sA[(lk + 6) * 132 + lm] = a1.z; sA[(lk + 7) * 132 + lm] = a1.w;
        sB[(lk + 0) * 132 + lm] = b0.x; sB[(lk + 1) * 132 + lm] = b0.y;
        sB[(lk + 2) * 132 + lm] = b0.z; sB[(lk + 3) * 132 + lm] = b0.w;
        sB[(lk + 4) * 132 + lm] = b1.x; sB[(lk + 5) * 132 + lm] = b1.y;
        sB[(lk + 6) * 132 + lm] = b1.z; sB[(lk + 7) * 132 + lm] = b1.w;
        __syncthreads();
#pragma unroll
        for (int kk = 0; kk < 16; kk++) {
            float af[8];
            *(float4*)af       = *(const float4*)&sA[kk * 132 + ty * 8];
            *(float4*)(af + 4) = *(const float4*)&sA[kk * 132 + ty * 8 + 4];
            unsigned long long bv[4];
#pragma unroll
            for (int jp = 0; jp < 4; jp++)
                bv[jp] = *(const unsigned long long*)&sB[kk * 132 + tx * 8 + jp * 2];
#pragma unroll
            for (int i = 0; i < 8; i++) {
                unsigned long long aa = pk2(af[i], af[i]);
#pragma unroll
                for (int jp = 0; jp < 4; jp++)
                    fma2(acc2[i][jp], aa, bv[jp]);
            }
        }
        __syncthreads();
        Aptr += 16; Bptr += 16;
    }
    float* outp = g_h1part + (size_t)blockIdx.y * (Bsz * HIDd);
#pragma unroll
    for (int i = 0; i < 8; i++)
#pragma unroll
        for (int jp = 0; jp < 4; jp++) {
            float2 v = upk2(acc2[i][jp]);
            size_t base = (size_t)(ty * 8 + i) * HIDd + ntile + tx * 8 + jp * 2;
            outp[base]     = v.x;
            outp[base + 1] = v.y;
        }
}

// ---------------- split-K reduce + bias + BN(eval) + ReLU ----------------
__global__ void k_bnrelu(const float* __restrict__ fb,
                         const float* __restrict__ g,
                         const float* __restrict__ beta) {
    int gid = blockIdx.x * 256 + threadIdx.x;
    float s = 0.f;
#pragma unroll
    for (int p = 0; p < SPLITK; p++) s += g_h1part[(size_t)p * (Bsz * HIDd) + gid];
    int o = gid & (HIDd - 1);
    float val = (s + fb[o]) * (g[o] * rsqrtf(1.f + 1e-5f)) + beta[o];
    g_h1[gid] = fmaxf(val, 0.f);
}

// ---------------- fc2: [128,2048] @ [2,2048]^T ----------------
__global__ void k_fc2(const float* __restrict__ w2, const float* __restrict__ b2,
                      float* __restrict__ out) {
    int b = blockIdx.x, tid = threadIdx.x;
    float a0 = 0.f, a1 = 0.f;
    for (int o = tid; o < HIDd; o += 256) {
        float h = g_h1[(size_t)b * HIDd + o];
        a0 += h * w2[o];
        a1 += h * w2[HIDd + o];
    }
    __shared__ float r0[256], r1[256];
    r0[tid] = a0; r1[tid] = a1;
    __syncthreads();
    for (int s = 128; s > 0; s >>= 1) {
        if (tid < s) { r0[tid] += r0[tid + s]; r1[tid] += r1[tid + s]; }
        __syncthreads();
    }
    if (tid == 0) {
        out[b * 2 + 0] = r0[0] + b2[0];
        out[b * 2 + 1] = r1[0] + b2[1];
    }
}

extern "C" void kernel_launch(void* const* d_in, const int* in_sizes, int n_in,
                              void* d_out, int out_size) {
    const float* x       = (const float*)d_in[0];
    const int*   ei      = (const int*)  d_in[1];
    const float* eattr   = (const float*)d_in[2];
    const float* tcn_w   = (const float*)d_in[3];
    const float* tcn_b   = (const float*)d_in[4];
    const float* lin_l_w = (const float*)d_in[5];
    const float* lin_l_b = (const float*)d_in[6];
    const float* lin_e_w = (const float*)d_in[7];
    const float* lin_e_b = (const float*)d_in[8];
    const float* att     = (const float*)d_in[9];
    const float* fc1_w   = (const float*)d_in[10];
    const float* fc1_b   = (const float*)d_in[11];
    const float* bn_g    = (const float*)d_in[12];
    const float* bn_b    = (const float*)d_in[13];
    const float* fc2_w   = (const float*)d_in[14];
    const float* fc2_b   = (const float*)d_in[15];
    float* out = (float*)d_out;

    k_csr<<<1, 512>>>(ei);
    k_tcn<<<dim3(4, Bsz), 128>>>(x, tcn_w, tcn_b);
    k_linl<<<dim3(2, Bsz), 256>>>(lin_l_w, lin_l_b);
    k_gat<<<dim3(NN, Bsz), 128>>>(eattr, lin_e_w, lin_e_b, att);
    k_fc1<<<dim3(16, SPLITK), 256>>>(fc1_w);
    k_bnrelu<<<(Bsz * HIDd) / 256, 256>>>(fc1_b, bn_g, bn_b);
    k_fc2<<<Bsz, 256>>>(fc2_w, fc2_b, out);
}

// round 3
// speedup vs baseline: 1.3710x; 1.3152x over previous
#include <cuda_runtime.h>
#include <math.h>

#define Bsz   128
#define Wd    128
#define FIN   64
#define NN    64
#define EE    4096
#define EDd   16
#define HC    128
#define FLATd 8192
#define HIDd  2048
#define SPLITK 16
#define CHUNK 128

// ---------------- scratch (static device globals; no allocation) ----------------
__device__ __align__(128) float g_xg[Bsz * NN * Wd];
__device__ __align__(128) float g_h[Bsz * NN * HC];
__device__ __align__(128) float g_xflat[Bsz * FLATd];
__device__ __align__(128) float g_h1part[SPLITK * Bsz * HIDd];
__device__ __align__(128) float g_h1[Bsz * HIDd];
__device__ int  g_csr_off[NN + 1];
__device__ int2 g_csr_es[EE];            // (edge_id, src_node)

// ---------------- f32x2 packed-FMA helpers ----------------
__device__ __forceinline__ unsigned long long pk2(float lo, float hi) {
    unsigned long long r;
    asm("mov.b64 %0, {%1,%2};" : "=l"(r) : "f"(lo), "f"(hi));
    return r;
}
__device__ __forceinline__ void fma2(unsigned long long& d,
                                     unsigned long long a, unsigned long long b) {
    asm("fma.rn.f32x2 %0, %1, %2, %0;" : "+l"(d) : "l"(a), "l"(b));
}
__device__ __forceinline__ float2 upk2(unsigned long long v) {
    float2 r;
    asm("mov.b64 {%0,%1}, %2;" : "=f"(r.x), "=f"(r.y) : "l"(v));
    return r;
}

// ---------------- CSR build ----------------
__global__ void k_csr(const int* __restrict__ ei) {
    __shared__ int cnt[NN];
    __shared__ int off[NN + 1];
    __shared__ int cur[NN];
    int tid = threadIdx.x;
    if (tid < NN) cnt[tid] = 0;
    __syncthreads();
    for (int e = tid; e < EE; e += blockDim.x)
        atomicAdd(&cnt[ei[EE + e]], 1);
    __syncthreads();
    if (tid == 0) {
        int run = 0;
        for (int k = 0; k < NN; k++) { off[k] = run; cur[k] = run; run += cnt[k]; }
        off[NN] = run;
    }
    __syncthreads();
    for (int e = tid; e < EE; e += blockDim.x) {
        int d = ei[EE + e];
        int pos = atomicAdd(&cur[d], 1);
        g_csr_es[pos] = make_int2(e, ei[e]);
    }
    if (tid <= NN) g_csr_off[tid] = off[tid];
}

// ---------------- TCN conv1d(k=3,pad=1) ----------------
__global__ void k_tcn(const float* __restrict__ x,
                      const float* __restrict__ tw,
                      const float* __restrict__ tb) {
    __shared__ float xs[FIN * 129];
    __shared__ float sw[16 * 192];
    int b = blockIdx.y, nc = blockIdx.x;
    int tid = threadIdx.x;
    const float* xb = x + (size_t)b * Wd * FIN;
    for (int idx = tid; idx < Wd * FIN; idx += 128) {
        int w = idx >> 6, i = idx & 63;
        xs[i * 129 + w] = xb[idx];
    }
    for (int idx = tid; idx < 16 * 192; idx += 128)
        sw[idx] = tw[nc * 16 * 192 + idx];
    __syncthreads();
    int w = tid;
    float acc[16];
#pragma unroll
    for (int nl = 0; nl < 16; nl++) acc[nl] = tb[nc * 16 + nl];
    for (int i = 0; i < FIN; i++) {
        float x0 = xs[i * 129 + w];
        float xm = (w > 0)   ? xs[i * 129 + w - 1] : 0.f;
        float xp = (w < 127) ? xs[i * 129 + w + 1] : 0.f;
#pragma unroll
        for (int nl = 0; nl < 16; nl++) {
            const float* wp = &sw[nl * 192 + i * 3];
            acc[nl] += xm * wp[0] + x0 * wp[1] + xp * wp[2];
        }
    }
#pragma unroll
    for (int nl = 0; nl < 16; nl++)
        g_xg[((size_t)b * NN + nc * 16 + nl) * Wd + w] = acc[nl];
}

// ---------------- lin_l projection ----------------
__global__ void k_linl(const float* __restrict__ lw, const float* __restrict__ lb) {
    __shared__ float xs[NN * 129];
    __shared__ float ws[64 * 33];
    int b = blockIdx.y, oc = blockIdx.x;
    int tid = threadIdx.x;
    for (int idx = tid; idx < NN * Wd; idx += 256) {
        int n = idx >> 7, w = idx & 127;
        xs[n * 129 + w] = g_xg[(size_t)b * NN * Wd + idx];
    }
    int tx = tid & 15, ty = tid >> 4;
    float acc[4][4];
#pragma unroll
    for (int i = 0; i < 4; i++)
#pragma unroll
        for (int j = 0; j < 4; j++) acc[i][j] = 0.f;
    for (int wc = 0; wc < 4; wc++) {
        __syncthreads();
        for (int idx = tid; idx < 64 * 32; idx += 256) {
            int ol = idx >> 5, wl = idx & 31;
            ws[ol * 33 + wl] = lw[(oc * 64 + ol) * Wd + wc * 32 + wl];
        }
        __syncthreads();
#pragma unroll 4
        for (int wl = 0; wl < 32; wl++) {
            float a[4], bb[4];
#pragma unroll
            for (int j = 0; j < 4; j++) a[j]  = xs[(ty * 4 + j) * 129 + wc * 32 + wl];
#pragma unroll
            for (int j = 0; j < 4; j++) bb[j] = ws[(tx * 4 + j) * 33 + wl];
#pragma unroll
            for (int i = 0; i < 4; i++)
#pragma unroll
                for (int j = 0; j < 4; j++) acc[i][j] += a[i] * bb[j];
        }
    }
#pragma unroll
    for (int i = 0; i < 4; i++)
#pragma unroll
        for (int j = 0; j < 4; j++) {
            int n = ty * 4 + i, o = oc * 64 + tx * 4 + j;
            g_h[((size_t)b * NN + n) * HC + o] = acc[i][j] + lb[o];
        }
}

// ---------------- GAT: chunked deferred softmax, smem-staged edge_attr ----------------
__global__ void __launch_bounds__(128) k_gat(const float* __restrict__ eattr,
                      const float* __restrict__ lew,
                      const float* __restrict__ leb,
                      const float* __restrict__ att) {
    __shared__ float4 ea_s[CHUNK * 4];   // [edge][quad] 8KB
    __shared__ int2   es_s[CHUNK];
    int n = blockIdx.x, b = blockIdx.y;
    int t = threadIdx.x;
    int lane = t & 31;
    const float4* w4 = (const float4*)(lew + t * EDd);
    float4 w0 = w4[0], w1 = w4[1], w2 = w4[2], w3 = w4[3];
    float eb = leb[t];
    float att_t = att[t];
    const float* hb = g_h + (size_t)b * NN * HC;
    float hd = hb[n * HC + t];

    int beg = g_csr_off[n], end = g_csr_off[n + 1];
    int deg = end - beg;
    const int2* lst = g_csr_es + beg;
    const float4* eab = (const float4*)eattr + (size_t)b * EE * 4;

    float m = -1e30f, den = 0.f, acc = 0.f;

    for (int base = 0; base < deg; base += CHUNK) {
        int cnt = min(CHUNK, deg - base);
        // ---- cooperative staging: deep-MLP coalesced burst ----
        if (t < cnt) es_s[t] = lst[base + t];
        __syncthreads();
        for (int idx = t; idx < cnt * 4; idx += 128)
            ea_s[idx] = eab[(size_t)es_s[idx >> 2].x * 4 + (idx & 3)];
        __syncthreads();

        // ---- pass 1: scores (no carried dependency) ----
        float sr[4] = {-1e30f, -1e30f, -1e30f, -1e30f};
#pragma unroll
        for (int q = 0; q < 4; q++) {
            int lim = min(32, cnt - q * 32);
            float sq = -1e30f;
            for (int jj = 0; jj < lim; jj++) {
                int j = q * 32 + jj;
                int2 p = es_s[j];
                float4 q0 = ea_s[j * 4 + 0];
                float4 q1 = ea_s[j * 4 + 1];
                float4 q2 = ea_s[j * 4 + 2];
                float4 q3 = ea_s[j * 4 + 3];
                float hs = hb[p.y * HC + t];
                float ev = eb
                    + q0.x * w0.x + q0.y * w0.y + q0.z * w0.z + q0.w * w0.w
                    + q1.x * w1.x + q1.y * w1.y + q1.z * w1.z + q1.w * w1.w
                    + q2.x * w2.x + q2.y * w2.y + q2.z * w2.z + q2.w * w2.w
                    + q3.x * w3.x + q3.y * w3.y + q3.z * w3.z + q3.w * w3.w;
                float z = hd + hs + ev;
                float xv = fmaxf(z, 0.01f * z) * att_t;
                xv += __shfl_xor_sync(0xffffffffu, xv, 16);
                xv += __shfl_xor_sync(0xffffffffu, xv, 8);
                xv += __shfl_xor_sync(0xffffffffu, xv, 4);
                xv += __shfl_xor_sync(0xffffffffu, xv, 2);
                xv += __shfl_xor_sync(0xffffffffu, xv, 1);
                if (jj == lane) sq = xv;
            }
            sr[q] = sq;
        }

        // ---- pass 2: chunk max / weights / denom ----
        float cm = fmaxf(fmaxf(sr[0], sr[1]), fmaxf(sr[2], sr[3]));
        cm = fmaxf(cm, __shfl_xor_sync(0xffffffffu, cm, 16));
        cm = fmaxf(cm, __shfl_xor_sync(0xffffffffu, cm, 8));
        cm = fmaxf(cm, __shfl_xor_sync(0xffffffffu, cm, 4));
        cm = fmaxf(cm, __shfl_xor_sync(0xffffffffu, cm, 2));
        cm = fmaxf(cm, __shfl_xor_sync(0xffffffffu, cm, 1));
        float mnew = fmaxf(m, cm);
        float resc = __expf(m - mnew);
        den *= resc; acc *= resc;
        m = mnew;
        float wr[4];
#pragma unroll
        for (int q = 0; q < 4; q++) wr[q] = __expf(sr[q] - m);
        float dl = wr[0] + wr[1] + wr[2] + wr[3];
        dl += __shfl_xor_sync(0xffffffffu, dl, 16);
        dl += __shfl_xor_sync(0xffffffffu, dl, 8);
        dl += __shfl_xor_sync(0xffffffffu, dl, 4);
        dl += __shfl_xor_sync(0xffffffffu, dl, 2);
        dl += __shfl_xor_sync(0xffffffffu, dl, 1);
        den += dl;

        // ---- pass 3: aggregation (fully pipelined) ----
#pragma unroll
        for (int q = 0; q < 4; q++) {
            int lim = min(32, cnt - q * 32);
            for (int jj = 0; jj < lim; jj++) {
                float wj = __shfl_sync(0xffffffffu, wr[q], jj);
                int2 p = es_s[q * 32 + jj];
                float hs = hb[p.y * HC + t];
                acc += wj * hs;
            }
        }
        __syncthreads();   // before ea_s reuse
    }

    float v = acc / (den + 1e-16f);
    float o = (v > 0.f) ? v : expm1f(v);
    g_xflat[(size_t)b * FLATd + n * HC + t] = o;
}

// ---------------- fc1: 128x2048x8192, tile 128m x 64n x 16k, split-K=16, FFMA2, 2-stage ----------------
__global__ void __launch_bounds__(256) k_fc1(const float* __restrict__ wq) {
    __shared__ float sA[2][16 * 132];
    __shared__ float sB[2][16 * 72];
    int ntile = blockIdx.x << 6;
    int k0 = blockIdx.y << 9;          // 512 K per split
    int tid = threadIdx.x;
    int arow = tid & 127, ak = (tid >> 7) << 3;
    int brow = tid & 63,  bk = (tid >> 6) << 2;
    int tx = tid & 15, ty = tid >> 4;

    const float* Ap = g_xflat + (size_t)arow * FLATd + k0 + ak;
    const float* Bp = wq + (size_t)(ntile + brow) * FLATd + k0 + bk;

    unsigned long long acc2[4][4];
#pragma unroll
    for (int i = 0; i < 4; i++)
#pragma unroll
        for (int j = 0; j < 4; j++) acc2[i][j] = 0ull;

    float4 a0 = *(const float4*)Ap;
    float4 a1 = *(const float4*)(Ap + 4);
    float4 b0 = *(const float4*)Bp;
    {
        sA[0][(ak + 0) * 132 + arow] = a0.x; sA[0][(ak + 1) * 132 + arow] = a0.y;
        sA[0][(ak + 2) * 132 + arow] = a0.z; sA[0][(ak + 3) * 132 + arow] = a0.w;
        sA[0][(ak + 4) * 132 + arow] = a1.x; sA[0][(ak + 5) * 132 + arow] = a1.y;
        sA[0][(ak + 6) * 132 + arow] = a1.z; sA[0][(ak + 7) * 132 + arow] = a1.w;
        sB[0][(bk + 0) * 72 + brow] = b0.x; sB[0][(bk + 1) * 72 + brow] = b0.y;
        sB[0][(bk + 2) * 72 + brow] = b0.z; sB[0][(bk + 3) * 72 + brow] = b0.w;
    }
    __syncthreads();

    for (int kt = 0; kt < 32; kt++) {
        int cur = kt & 1;
        if (kt < 31) {                       // prefetch next tile (overlaps compute)
            Ap += 16; Bp += 16;
            a0 = *(const float4*)Ap;
            a1 = *(const float4*)(Ap + 4);
            b0 = *(const float4*)Bp;
        }
#pragma unroll
        for (int kk = 0; kk < 16; kk++) {
            float4 afa = *(const float4*)&sA[cur][kk * 132 + ty * 8];
            float4 afb = *(const float4*)&sA[cur][kk * 132 + ty * 8 + 4];
            float4 bq  = *(const float4*)&sB[cur][kk * 72 + tx * 4];
            unsigned long long aa[4] = { pk2(afa.x, afa.y), pk2(afa.z, afa.w),
                                         pk2(afb.x, afb.y), pk2(afb.z, afb.w) };
            unsigned long long bb[4] = { pk2(bq.x, bq.x), pk2(bq.y, bq.y),
                                         pk2(bq.z, bq.z), pk2(bq.w, bq.w) };
#pragma unroll
            for (int mi = 0; mi < 4; mi++)
#pragma unroll
                for (int j = 0; j < 4; j++)
                    fma2(acc2[mi][j], aa[mi], bb[j]);
        }
        if (kt < 31) {
            int nxt = cur ^ 1;
            sA[nxt][(ak + 0) * 132 + arow] = a0.x; sA[nxt][(ak + 1) * 132 + arow] = a0.y;
            sA[nxt][(ak + 2) * 132 + arow] = a0.z; sA[nxt][(ak + 3) * 132 + arow] = a0.w;
            sA[nxt][(ak + 4) * 132 + arow] = a1.x; sA[nxt][(ak + 5) * 132 + arow] = a1.y;
            sA[nxt][(ak + 6) * 132 + arow] = a1.z; sA[nxt][(ak + 7) * 132 + arow] = a1.w;
            sB[nxt][(bk + 0) * 72 + brow] = b0.x; sB[nxt][(bk + 1) * 72 + brow] = b0.y;
            sB[nxt][(bk + 2) * 72 + brow] = b0.z; sB[nxt][(bk + 3) * 72 + brow] = b0.w;
        }
        __syncthreads();
    }

    float* outp = g_h1part + (size_t)blockIdx.y * (Bsz * HIDd);
#pragma unroll
    for (int mi = 0; mi < 4; mi++)
#pragma unroll
        for (int j = 0; j < 4; j++) {
            float2 v = upk2(acc2[mi][j]);
            int mrow = ty * 8 + 2 * mi;
            int ncol = ntile + tx * 4 + j;
            outp[(size_t)mrow * HIDd + ncol]       = v.x;
            outp[(size_t)(mrow + 1) * HIDd + ncol] = v.y;
        }
}

// ---------------- split-K reduce + bias + BN(eval) + ReLU ----------------
__global__ void k_bnrelu(const float* __restrict__ fb,
                         const float* __restrict__ g,
                         const float* __restrict__ beta) {
    int gid = blockIdx.x * 256 + threadIdx.x;
    float s = 0.f;
#pragma unroll
    for (int p = 0; p < SPLITK; p++) s += g_h1part[(size_t)p * (Bsz * HIDd) + gid];
    int o = gid & (HIDd - 1);
    float val = (s + fb[o]) * (g[o] * rsqrtf(1.f + 1e-5f)) + beta[o];
    g_h1[gid] = fmaxf(val, 0.f);
}

// ---------------- fc2 ----------------
__global__ void k_fc2(const float* __restrict__ w2, const float* __restrict__ b2,
                      float* __restrict__ out) {
    int b = blockIdx.x, tid = threadIdx.x;
    float a0 = 0.f, a1 = 0.f;
    for (int o = tid; o < HIDd; o += 256) {
        float h = g_h1[(size_t)b * HIDd + o];
        a0 += h * w2[o];
        a1 += h * w2[HIDd + o];
    }
    __shared__ float r0[256], r1[256];
    r0[tid] = a0; r1[tid] = a1;
    __syncthreads();
    for (int s = 128; s > 0; s >>= 1) {
        if (tid < s) { r0[tid] += r0[tid + s]; r1[tid] += r1[tid + s]; }
        __syncthreads();
    }
    if (tid == 0) {
        out[b * 2 + 0] = r0[0] + b2[0];
        out[b * 2 + 1] = r1[0] + b2[1];
    }
}

extern "C" void kernel_launch(void* const* d_in, const int* in_sizes, int n_in,
                              void* d_out, int out_size) {
    const float* x       = (const float*)d_in[0];
    const int*   ei      = (const int*)  d_in[1];
    const float* eattr   = (const float*)d_in[2];
    const float* tcn_w   = (const float*)d_in[3];
    const float* tcn_b   = (const float*)d_in[4];
    const float* lin_l_w = (const float*)d_in[5];
    const float* lin_l_b = (const float*)d_in[6];
    const float* lin_e_w = (const float*)d_in[7];
    const float* lin_e_b = (const float*)d_in[8];
    const float* att     = (const float*)d_in[9];
    const float* fc1_w   = (const float*)d_in[10];
    const float* fc1_b   = (const float*)d_in[11];
    const float* bn_g    = (const float*)d_in[12];
    const float* bn_b    = (const float*)d_in[13];
    const float* fc2_w   = (const float*)d_in[14];
    const float* fc2_b   = (const float*)d_in[15];
    float* out = (float*)d_out;

    k_csr<<<1, 512>>>(ei);
    k_tcn<<<dim3(4, Bsz), 128>>>(x, tcn_w, tcn_b);
    k_linl<<<dim3(2, Bsz), 256>>>(lin_l_w, lin_l_b);
    k_gat<<<dim3(NN, Bsz), 128>>>(eattr, lin_e_w, lin_e_b, att);
    k_fc1<<<dim3(32, SPLITK), 256>>>(fc1_w);
    k_bnrelu<<<(Bsz * HIDd) / 256, 256>>>(fc1_b, bn_g, bn_b);
    k_fc2<<<Bsz, 256>>>(fc2_w, fc2_b, out);
}